// round 4
// baseline (speedup 1.0000x reference)
#include <cuda_runtime.h>
#include <cuda_bf16.h>
#include <math.h>
#include <stdint.h>

#define BATCHN 2
#define SEQLENN 4096
#define DIMN 1024
#define DSTATE 64
#define DCONVN 4
#define DINNER 2048
#define NHEADSN 32
#define CONVD 2176          // D_INNER + 2*D_STATE
#define DPROJ 4256          // 2*D_INNER + 2*D_STATE + NHEADS
#define NROWS (BATCHN*SEQLENN)   // 8192
#define NSEG 16             // time segments per sequence
#define SEGL (SEQLENN/NSEG) // 256
#define TCH 32              // timesteps staged per chunk
#define EPSV 1e-5f

// ------------------------- scratch (no allocs allowed) -------------------------
__device__ float g_zxbcdt[(size_t)NROWS * DPROJ];            // in_proj output
__device__ float g_xBCc[(size_t)NROWS * CONVD];              // conv+silu output
__device__ float g_dt[(size_t)NROWS * NHEADSN];              // softplus dt
__device__ float g_y[(size_t)NROWS * DINNER];                // scan output y
__device__ float g_state[(size_t)BATCHN * NHEADSN * NSEG * DSTATE * 64]; // local seg states
__device__ float g_hin[(size_t)BATCHN * NHEADSN * NSEG * DSTATE * 64];   // carry-in states
__device__ float g_acum[(size_t)BATCHN * NHEADSN * SEQLENN]; // cumulative dA within segment
__device__ float g_yn[(size_t)NROWS * DINNER];               // gated+normed y
__device__ float g_H[(size_t)NROWS * DIMN];                  // out_proj output
__device__ float g_HKV[(size_t)NROWS * DINNER];              // to_h output

// ------------------------- bf16 helpers -------------------------
__device__ __forceinline__ uint32_t pack_hi(float a, float b, float& ra, float& rb) {
    __nv_bfloat162 h = __floats2bfloat162_rn(a, b);
    ra = a - __bfloat162float(h.x);
    rb = b - __bfloat162float(h.y);
    return *(uint32_t*)&h;
}
__device__ __forceinline__ uint32_t pack_lo(float a, float b) {
    __nv_bfloat162 h = __floats2bfloat162_rn(a, b);
    return *(uint32_t*)&h;
}

#define MMA_BF16(c, a, b) \
    asm volatile("mma.sync.aligned.m16n8k16.row.col.f32.bf16.bf16.f32 " \
        "{%0,%1,%2,%3}, {%4,%5,%6,%7}, {%8,%9}, {%0,%1,%2,%3};" \
        : "+f"((c)[0]), "+f"((c)[1]), "+f"((c)[2]), "+f"((c)[3]) \
        : "r"((a)[0]), "r"((a)[1]), "r"((a)[2]), "r"((a)[3]), \
          "r"((b)[0]), "r"((b)[1]))

// ------------------------- tensor-core GEMM: C[M,N] = A[M,K] @ B[N,K]^T -------------------------
__global__ __launch_bounds__(256) void gemm_nt_tc(
    const float* __restrict__ A, const float* __restrict__ B,
    float* __restrict__ C, int M, int N, int K)
{
    __shared__ uint32_t Ah[8][136];
    __shared__ uint32_t Al[8][136];
    __shared__ uint32_t Bh[8][136];
    __shared__ uint32_t Bl[8][136];

    const int tid  = threadIdx.x;
    const int bm   = blockIdx.y * 128;
    const int bn   = blockIdx.x * 128;
    const int lane = tid & 31;
    const int warp = tid >> 5;
    const int wm   = (warp >> 2) * 64;
    const int wn   = (warp & 3) * 32;
    const int grp  = lane >> 2;
    const int qid  = lane & 3;

    const int sr0 = tid >> 2;
    const int sr1 = sr0 + 64;
    const int skk = (tid & 3) << 2;
    const int spp = skk >> 1;

    float acc[4][4][4];
#pragma unroll
    for (int i = 0; i < 4; i++)
#pragma unroll
        for (int j = 0; j < 4; j++)
#pragma unroll
            for (int e = 0; e < 4; e++) acc[i][j][e] = 0.f;

    float4 av[2], bv[2];
    {
        const float4 z4 = make_float4(0.f, 0.f, 0.f, 0.f);
        av[0] = (bm + sr0 < M) ? *(const float4*)(A + (size_t)(bm + sr0) * K + skk) : z4;
        av[1] = (bm + sr1 < M) ? *(const float4*)(A + (size_t)(bm + sr1) * K + skk) : z4;
        bv[0] = (bn + sr0 < N) ? *(const float4*)(B + (size_t)(bn + sr0) * K + skk) : z4;
        bv[1] = (bn + sr1 < N) ? *(const float4*)(B + (size_t)(bn + sr1) * K + skk) : z4;
    }

    for (int k0 = 0; k0 < K; k0 += 16) {
#pragma unroll
        for (int half = 0; half < 2; half++) {
            int r = half ? sr1 : sr0;
            float4 v = av[half];
            float rx, ry, rz, rw;
            Ah[spp    ][r] = pack_hi(v.x, v.y, rx, ry);
            Ah[spp + 1][r] = pack_hi(v.z, v.w, rz, rw);
            Al[spp    ][r] = pack_lo(rx, ry);
            Al[spp + 1][r] = pack_lo(rz, rw);
            v = bv[half];
            Bh[spp    ][r] = pack_hi(v.x, v.y, rx, ry);
            Bh[spp + 1][r] = pack_hi(v.z, v.w, rz, rw);
            Bl[spp    ][r] = pack_lo(rx, ry);
            Bl[spp + 1][r] = pack_lo(rz, rw);
        }
        __syncthreads();

        if (k0 + 16 < K) {
            const float4 z4 = make_float4(0.f, 0.f, 0.f, 0.f);
            int kn = k0 + 16 + skk;
            av[0] = (bm + sr0 < M) ? *(const float4*)(A + (size_t)(bm + sr0) * K + kn) : z4;
            av[1] = (bm + sr1 < M) ? *(const float4*)(A + (size_t)(bm + sr1) * K + kn) : z4;
            bv[0] = (bn + sr0 < N) ? *(const float4*)(B + (size_t)(bn + sr0) * K + kn) : z4;
            bv[1] = (bn + sr1 < N) ? *(const float4*)(B + (size_t)(bn + sr1) * K + kn) : z4;
        }

        uint32_t ah[4][4], al[4][4];
#pragma unroll
        for (int mf = 0; mf < 4; mf++) {
            int r0 = wm + mf * 16 + grp;
            ah[mf][0] = Ah[qid    ][r0];
            ah[mf][1] = Ah[qid    ][r0 + 8];
            ah[mf][2] = Ah[qid + 4][r0];
            ah[mf][3] = Ah[qid + 4][r0 + 8];
            al[mf][0] = Al[qid    ][r0];
            al[mf][1] = Al[qid    ][r0 + 8];
            al[mf][2] = Al[qid + 4][r0];
            al[mf][3] = Al[qid + 4][r0 + 8];
        }
        uint32_t bh[4][2], bl[4][2];
#pragma unroll
        for (int nf = 0; nf < 4; nf++) {
            int c0 = wn + nf * 8 + grp;
            bh[nf][0] = Bh[qid    ][c0];
            bh[nf][1] = Bh[qid + 4][c0];
            bl[nf][0] = Bl[qid    ][c0];
            bl[nf][1] = Bl[qid + 4][c0];
        }
#pragma unroll
        for (int mf = 0; mf < 4; mf++)
#pragma unroll
            for (int nf = 0; nf < 4; nf++) {
                MMA_BF16(acc[mf][nf], ah[mf], bh[nf]);
                MMA_BF16(acc[mf][nf], ah[mf], bl[nf]);
                MMA_BF16(acc[mf][nf], al[mf], bh[nf]);
            }
        __syncthreads();
    }

#pragma unroll
    for (int mf = 0; mf < 4; mf++) {
        int gr0 = bm + wm + mf * 16 + grp;
        int gr1 = gr0 + 8;
#pragma unroll
        for (int nf = 0; nf < 4; nf++) {
            int gc = bn + wn + nf * 8 + 2 * qid;
            if (gc < N) {
                if (gr0 < M) {
                    C[(size_t)gr0 * N + gc]     = acc[mf][nf][0];
                    C[(size_t)gr0 * N + gc + 1] = acc[mf][nf][1];
                }
                if (gr1 < M) {
                    C[(size_t)gr1 * N + gc]     = acc[mf][nf][2];
                    C[(size_t)gr1 * N + gc + 1] = acc[mf][nf][3];
                }
            }
        }
    }
}

// ------------------------- dt = softplus(dt_raw + dt_bias) -------------------------
__global__ void dt_kernel(const float* __restrict__ dt_bias)
{
    int idx = blockIdx.x * blockDim.x + threadIdx.x;
    if (idx >= NROWS * NHEADSN) return;
    int h = idx & (NHEADSN - 1);
    int row = idx >> 5;
    float v = g_zxbcdt[(size_t)row * DPROJ + (DINNER + CONVD) + h] + dt_bias[h];
    float sp = (v > 20.f) ? v : log1pf(expf(v));
    g_dt[idx] = sp;
}

// ------------------------- depthwise causal conv (w=4) + bias + SiLU -------------------------
__global__ void conv_silu_kernel(const float* __restrict__ cw, const float* __restrict__ cb)
{
    size_t idx = (size_t)blockIdx.x * blockDim.x + threadIdx.x;
    if (idx >= (size_t)NROWS * CONVD) return;
    int c = (int)(idx % CONVD);
    size_t bl = idx / CONVD;
    int l = (int)(bl % SEQLENN);
    int b = (int)(bl / SEQLENN);
    float acc = cb[c];
#pragma unroll
    for (int k = 0; k < DCONVN; k++) {
        int lt = l - (DCONVN - 1) + k;
        if (lt >= 0)
            acc = fmaf(cw[c * DCONVN + k],
                       g_zxbcdt[(size_t)(b * SEQLENN + lt) * DPROJ + DINNER + c], acc);
    }
    float sg = 1.f / (1.f + expf(-acc));
    g_xBCc[idx] = acc * sg;
}

// ------------------------- pass 1: per-segment local scan -------------------------
// grid = B*NHEADS*NSEG. thread: p = tid>>2 (0..63), sub = tid&3 owns 16 states.
__global__ __launch_bounds__(256) void scan_seg_kernel(const float* __restrict__ A_log)
{
    const int bid = blockIdx.x;
    const int seg = bid & (NSEG - 1);
    const int h   = (bid >> 4) & (NHEADSN - 1);
    const int b   = bid >> 9;
    const int tid = threadIdx.x;
    const int p   = tid >> 2;
    const int sub = tid & 3;
    const float Ah = -expf(A_log[h]);
    const int bh = b * NHEADSN + h;
    const int rbase = b * SEQLENN + seg * SEGL;

    __shared__ __align__(16) float s_x[TCH][64];
    __shared__ __align__(16) float s_B[TCH][64];
    __shared__ __align__(16) float s_C[TCH][64];
    __shared__ __align__(16) float s_y[TCH][64];
    __shared__ float s_dt[TCH];
    __shared__ float s_dA[TCH];
    __shared__ float s_ac[TCH];
    __shared__ float s_run;

    if (tid == 0) s_run = 1.f;

    float hreg[16];
#pragma unroll
    for (int j = 0; j < 16; j++) hreg[j] = 0.f;

    for (int t0 = 0; t0 < SEGL; t0 += TCH) {
        for (int i = tid; i < TCH * 64; i += 256) {
            int t = i >> 6, pp = i & 63;
            size_t ro = (size_t)(rbase + t0 + t) * CONVD;
            s_x[t][pp] = g_xBCc[ro + h * 64 + pp];
            s_B[t][pp] = g_xBCc[ro + DINNER + pp];
            s_C[t][pp] = g_xBCc[ro + DINNER + DSTATE + pp];
        }
        if (tid < TCH) {
            float dtv = g_dt[(size_t)(rbase + t0 + tid) * NHEADSN + h];
            s_dt[tid] = dtv;
            s_dA[tid] = expf(dtv * Ah);
        }
        __syncthreads();
        if (tid == 0) {
            float run = s_run;
#pragma unroll
            for (int t = 0; t < TCH; t++) { run *= s_dA[t]; s_ac[t] = run; }
            s_run = run;
        }
#pragma unroll 2
        for (int t = 0; t < TCH; t++) {
            float dA = s_dA[t];
            float dtx = s_dt[t] * s_x[t][p];
            float y = 0.f;
            const float4* Bq = (const float4*)&s_B[t][sub * 16];
            const float4* Cq = (const float4*)&s_C[t][sub * 16];
#pragma unroll
            for (int q = 0; q < 4; q++) {
                float4 Bv = Bq[q];
                float4 Cv = Cq[q];
                hreg[q*4+0] = fmaf(hreg[q*4+0], dA, dtx * Bv.x); y = fmaf(hreg[q*4+0], Cv.x, y);
                hreg[q*4+1] = fmaf(hreg[q*4+1], dA, dtx * Bv.y); y = fmaf(hreg[q*4+1], Cv.y, y);
                hreg[q*4+2] = fmaf(hreg[q*4+2], dA, dtx * Bv.z); y = fmaf(hreg[q*4+2], Cv.z, y);
                hreg[q*4+3] = fmaf(hreg[q*4+3], dA, dtx * Bv.w); y = fmaf(hreg[q*4+3], Cv.w, y);
            }
            y += __shfl_down_sync(0xffffffffu, y, 2, 4);
            y += __shfl_down_sync(0xffffffffu, y, 1, 4);
            if (sub == 0) s_y[t][p] = y;
        }
        __syncthreads();
        for (int i = tid; i < TCH * 64; i += 256) {
            int t = i >> 6, pp = i & 63;
            g_y[(size_t)(rbase + t0 + t) * DINNER + h * 64 + pp] = s_y[t][pp];
        }
        if (tid < TCH)
            g_acum[(size_t)bh * SEQLENN + seg * SEGL + t0 + tid] = s_ac[tid];
        __syncthreads();
    }

    // write local final state [p][n]
    float* st = g_state + ((size_t)bh * NSEG + seg) * (64 * DSTATE) + p * DSTATE + sub * 16;
#pragma unroll
    for (int q = 0; q < 4; q++)
        *(float4*)(st + q * 4) = make_float4(hreg[q*4+0], hreg[q*4+1], hreg[q*4+2], hreg[q*4+3]);
}

// ------------------------- pass 2: prefix over segment states -------------------------
// grid = B*NHEADS, 256 threads, each thread owns 16 consecutive state elems.
__global__ __launch_bounds__(256) void state_combine_kernel()
{
    const int bh = blockIdx.x;
    const int tid = threadIdx.x;
    const size_t base = (size_t)bh * NSEG * (64 * DSTATE);
    float4 hin[4];
#pragma unroll
    for (int q = 0; q < 4; q++) hin[q] = make_float4(0.f, 0.f, 0.f, 0.f);

    for (int seg = 1; seg < NSEG; seg++) {
        float ap = g_acum[(size_t)bh * SEQLENN + seg * SEGL - 1];
        const float4* sl = (const float4*)(g_state + base + (size_t)(seg - 1) * (64 * DSTATE) + tid * 16);
        float4* ho = (float4*)(g_hin + base + (size_t)seg * (64 * DSTATE) + tid * 16);
#pragma unroll
        for (int q = 0; q < 4; q++) {
            float4 s = sl[q];
            hin[q].x = fmaf(hin[q].x, ap, s.x);
            hin[q].y = fmaf(hin[q].y, ap, s.y);
            hin[q].z = fmaf(hin[q].z, ap, s.z);
            hin[q].w = fmaf(hin[q].w, ap, s.w);
            ho[q] = hin[q];
        }
    }
}

// ------------------------- pass 3: apply carry-in: y += acum(t) * C_t . H_in -------------------------
// grid = B*NHEADS*(NSEG-1) (seg 0 skipped).
__global__ __launch_bounds__(256) void carry_apply_kernel()
{
    const int bid = blockIdx.x;
    const int seg = 1 + (bid % (NSEG - 1));
    const int hb  = bid / (NSEG - 1);
    const int h   = hb & (NHEADSN - 1);
    const int b   = hb >> 5;
    const int tid = threadIdx.x;
    const int p   = tid >> 2;
    const int sub = tid & 3;
    const int bh  = b * NHEADSN + h;
    const int rbase = b * SEQLENN + seg * SEGL;

    __shared__ __align__(16) float s_hin[64][68];   // padded
    __shared__ __align__(16) float s_C[TCH][64];
    __shared__ __align__(16) float s_y[TCH][64];
    __shared__ float s_ac[TCH];

    {
        const float* hi = g_hin + ((size_t)bh * NSEG + seg) * (64 * DSTATE);
        for (int i = tid; i < 64 * DSTATE / 4; i += 256) {
            int r = i >> 4;            // row p (16 float4 per row)
            int c = (i & 15) << 2;
            float4 v = *(const float4*)(hi + r * DSTATE + c);
            s_hin[r][c] = v.x; s_hin[r][c+1] = v.y; s_hin[r][c+2] = v.z; s_hin[r][c+3] = v.w;
        }
    }
    __syncthreads();

    for (int t0 = 0; t0 < SEGL; t0 += TCH) {
        for (int i = tid; i < TCH * 64; i += 256) {
            int t = i >> 6, pp = i & 63;
            s_C[t][pp] = g_xBCc[(size_t)(rbase + t0 + t) * CONVD + DINNER + DSTATE + pp];
        }
        if (tid < TCH)
            s_ac[tid] = g_acum[(size_t)bh * SEQLENN + seg * SEGL + t0 + tid];
        __syncthreads();
#pragma unroll 2
        for (int t = 0; t < TCH; t++) {
            float y = 0.f;
            const float4* Cq = (const float4*)&s_C[t][sub * 16];
            const float* hp = &s_hin[p][sub * 16];
#pragma unroll
            for (int q = 0; q < 4; q++) {
                float4 Cv = Cq[q];
                const float4 hv = *(const float4*)(hp + q * 4);
                y = fmaf(hv.x, Cv.x, y);
                y = fmaf(hv.y, Cv.y, y);
                y = fmaf(hv.z, Cv.z, y);
                y = fmaf(hv.w, Cv.w, y);
            }
            y += __shfl_down_sync(0xffffffffu, y, 2, 4);
            y += __shfl_down_sync(0xffffffffu, y, 1, 4);
            if (sub == 0) s_y[t][p] = y * s_ac[t];
        }
        __syncthreads();
        for (int i = tid; i < TCH * 64; i += 256) {
            int t = i >> 6, pp = i & 63;
            size_t yi = (size_t)(rbase + t0 + t) * DINNER + h * 64 + pp;
            g_y[yi] += s_y[t][pp];
        }
        __syncthreads();
    }
}

// ------------------------- D*x, gate with silu(z), RMSNorm -------------------------
__global__ __launch_bounds__(256) void gate_norm_kernel(
    const float* __restrict__ Dp, const float* __restrict__ norm_w)
{
    const int row = blockIdx.x;
    const int tid = threadIdx.x;
    float vals[8];
    float ss = 0.f;
#pragma unroll
    for (int j = 0; j < 8; j++) {
        int c = tid + j * 256;
        float y = g_y[(size_t)row * DINNER + c];
        int hh = c >> 6;
        float xv = g_xBCc[(size_t)row * CONVD + c];
        y = fmaf(Dp[hh], xv, y);
        float zv = g_zxbcdt[(size_t)row * DPROJ + c];
        float g = zv / (1.f + expf(-zv));
        float v = y * g;
        vals[j] = v;
        ss = fmaf(v, v, ss);
    }
    __shared__ float red[32];
    for (int o = 16; o; o >>= 1) ss += __shfl_down_sync(0xffffffffu, ss, o);
    if ((tid & 31) == 0) red[tid >> 5] = ss;
    __syncthreads();
    if (tid < 32) {
        float s2 = (tid < 8) ? red[tid] : 0.f;
        for (int o = 4; o; o >>= 1) s2 += __shfl_down_sync(0xffffffffu, s2, o);
        if (tid == 0) red[0] = s2;
    }
    __syncthreads();
    float scale = rsqrtf(red[0] / (float)DINNER + EPSV);
#pragma unroll
    for (int j = 0; j < 8; j++) {
        int c = tid + j * 256;
        g_yn[(size_t)row * DINNER + c] = vals[j] * scale * norm_w[c];
    }
}

// ------------------------- split HKV -> HK | HV -------------------------
__global__ void split_kernel(float* __restrict__ out)
{
    size_t idx = (size_t)blockIdx.x * blockDim.x + threadIdx.x;
    if (idx >= (size_t)NROWS * DINNER) return;
    size_t row = idx / DINNER;
    int c = (int)(idx % DINNER);
    float v = g_HKV[idx];
    if (c < DIMN)
        out[row * DIMN + c] = v;
    else
        out[(size_t)NROWS * DIMN + row * DIMN + (c - DIMN)] = v;
}

// ------------------------- launch -------------------------
extern "C" void kernel_launch(void* const* d_in, const int* in_sizes, int n_in,
                              void* d_out, int out_size)
{
    const float* X          = (const float*)d_in[0];
    const float* in_proj_w  = (const float*)d_in[1];
    const float* conv_w     = (const float*)d_in[2];
    const float* conv_b     = (const float*)d_in[3];
    const float* dt_bias    = (const float*)d_in[4];
    const float* A_log      = (const float*)d_in[5];
    const float* Dp         = (const float*)d_in[6];
    const float* norm_w     = (const float*)d_in[7];
    const float* out_proj_w = (const float*)d_in[8];
    const float* to_h_w     = (const float*)d_in[9];
    float* out = (float*)d_out;

    float *zx, *yn, *H, *HKV;
    cudaGetSymbolAddress((void**)&zx,  g_zxbcdt);
    cudaGetSymbolAddress((void**)&yn,  g_yn);
    cudaGetSymbolAddress((void**)&H,   g_H);
    cudaGetSymbolAddress((void**)&HKV, g_HKV);

    // 1) zxbcdt = X @ in_proj_w^T
    gemm_nt_tc<<<dim3((DPROJ + 127) / 128, NROWS / 128), 256>>>(X, in_proj_w, zx, NROWS, DPROJ, DIMN);
    // 2) dt = softplus(dt_raw + bias)
    dt_kernel<<<(NROWS * NHEADSN + 255) / 256, 256>>>(dt_bias);
    // 3) depthwise conv + silu
    conv_silu_kernel<<<(int)(((size_t)NROWS * CONVD + 255) / 256), 256>>>(conv_w, conv_b);
    // 4) segmented scan: local pass, state prefix, carry apply
    scan_seg_kernel<<<BATCHN * NHEADSN * NSEG, 256>>>(A_log);
    state_combine_kernel<<<BATCHN * NHEADSN, 256>>>();
    carry_apply_kernel<<<BATCHN * NHEADSN * (NSEG - 1), 256>>>();
    // 5) gate + rmsnorm
    gate_norm_kernel<<<NROWS, 256>>>(Dp, norm_w);
    // 6) H = yn @ out_proj_w^T
    gemm_nt_tc<<<dim3(DIMN / 128, NROWS / 128), 256>>>(yn, out_proj_w, H, NROWS, DIMN, DINNER);
    // 7) HKV = H @ to_h_w^T
    gemm_nt_tc<<<dim3(DINNER / 128, NROWS / 128), 256>>>(H, to_h_w, HKV, NROWS, DINNER, DIMN);
    // 8) split into HK | HV
    split_kernel<<<(int)(((size_t)NROWS * DINNER + 255) / 256), 256>>>(out);
}

// round 5
// speedup vs baseline: 1.1467x; 1.1467x over previous
#include <cuda_runtime.h>
#include <cuda_bf16.h>
#include <math.h>
#include <stdint.h>

#define BATCHN 2
#define SEQLENN 4096
#define DIMN 1024
#define DSTATE 64
#define DCONVN 4
#define DINNER 2048
#define NHEADSN 32
#define CONVD 2176          // D_INNER + 2*D_STATE
#define DPROJ 4256          // 2*D_INNER + 2*D_STATE + NHEADS
#define NROWS (BATCHN*SEQLENN)   // 8192
#define NSEG 16             // time segments per sequence
#define SEGL (SEQLENN/NSEG) // 256
#define TCH 32              // timesteps staged per chunk
#define EPSV 1e-5f

// ------------------------- scratch (no allocs allowed) -------------------------
__device__ float g_zxbcdt[(size_t)NROWS * DPROJ];            // in_proj output
__device__ float g_xBCc[(size_t)NROWS * CONVD];              // conv+silu output
__device__ float g_dt[(size_t)NROWS * NHEADSN];              // softplus dt
__device__ float g_y[(size_t)NROWS * DINNER];                // scan output y
__device__ float g_state[(size_t)BATCHN * NHEADSN * NSEG * DSTATE * 64]; // local seg states
__device__ float g_hin[(size_t)BATCHN * NHEADSN * NSEG * DSTATE * 64];   // carry-in states
__device__ float g_acum[(size_t)BATCHN * NHEADSN * SEQLENN]; // cumulative dA within segment
__device__ float g_yn[(size_t)NROWS * DINNER];               // gated+normed y
__device__ float g_H[(size_t)NROWS * DIMN];                  // out_proj output

// ------------------------- bf16 helpers -------------------------
__device__ __forceinline__ uint32_t pack_hi(float a, float b, float& ra, float& rb) {
    __nv_bfloat162 h = __floats2bfloat162_rn(a, b);
    ra = a - __bfloat162float(h.x);
    rb = b - __bfloat162float(h.y);
    return *(uint32_t*)&h;
}
__device__ __forceinline__ uint32_t pack_lo(float a, float b) {
    __nv_bfloat162 h = __floats2bfloat162_rn(a, b);
    return *(uint32_t*)&h;
}

#define MMA_BF16(c, a, b) \
    asm volatile("mma.sync.aligned.m16n8k16.row.col.f32.bf16.bf16.f32 " \
        "{%0,%1,%2,%3}, {%4,%5,%6,%7}, {%8,%9}, {%0,%1,%2,%3};" \
        : "+f"((c)[0]), "+f"((c)[1]), "+f"((c)[2]), "+f"((c)[3]) \
        : "r"((a)[0]), "r"((a)[1]), "r"((a)[2]), "r"((a)[3]), \
          "r"((b)[0]), "r"((b)[1]))

// ------------------------- tensor-core GEMM: C[M,N] = A[M,K] @ B[N,K]^T -------------------------
__global__ __launch_bounds__(256) void gemm_nt_tc(
    const float* __restrict__ A, const float* __restrict__ B,
    float* __restrict__ C, int M, int N, int K)
{
    __shared__ uint32_t Ah[8][136];
    __shared__ uint32_t Al[8][136];
    __shared__ uint32_t Bh[8][136];
    __shared__ uint32_t Bl[8][136];

    const int tid  = threadIdx.x;
    const int bm   = blockIdx.y * 128;
    const int bn   = blockIdx.x * 128;
    const int lane = tid & 31;
    const int warp = tid >> 5;
    const int wm   = (warp >> 2) * 64;
    const int wn   = (warp & 3) * 32;
    const int grp  = lane >> 2;
    const int qid  = lane & 3;

    const int sr0 = tid >> 2;
    const int sr1 = sr0 + 64;
    const int skk = (tid & 3) << 2;
    const int spp = skk >> 1;

    float acc[4][4][4];
#pragma unroll
    for (int i = 0; i < 4; i++)
#pragma unroll
        for (int j = 0; j < 4; j++)
#pragma unroll
            for (int e = 0; e < 4; e++) acc[i][j][e] = 0.f;

    float4 av[2], bv[2];
    {
        const float4 z4 = make_float4(0.f, 0.f, 0.f, 0.f);
        av[0] = (bm + sr0 < M) ? *(const float4*)(A + (size_t)(bm + sr0) * K + skk) : z4;
        av[1] = (bm + sr1 < M) ? *(const float4*)(A + (size_t)(bm + sr1) * K + skk) : z4;
        bv[0] = (bn + sr0 < N) ? *(const float4*)(B + (size_t)(bn + sr0) * K + skk) : z4;
        bv[1] = (bn + sr1 < N) ? *(const float4*)(B + (size_t)(bn + sr1) * K + skk) : z4;
    }

    for (int k0 = 0; k0 < K; k0 += 16) {
#pragma unroll
        for (int half = 0; half < 2; half++) {
            int r = half ? sr1 : sr0;
            float4 v = av[half];
            float rx, ry, rz, rw;
            Ah[spp    ][r] = pack_hi(v.x, v.y, rx, ry);
            Ah[spp + 1][r] = pack_hi(v.z, v.w, rz, rw);
            Al[spp    ][r] = pack_lo(rx, ry);
            Al[spp + 1][r] = pack_lo(rz, rw);
            v = bv[half];
            Bh[spp    ][r] = pack_hi(v.x, v.y, rx, ry);
            Bh[spp + 1][r] = pack_hi(v.z, v.w, rz, rw);
            Bl[spp    ][r] = pack_lo(rx, ry);
            Bl[spp + 1][r] = pack_lo(rz, rw);
        }
        __syncthreads();

        if (k0 + 16 < K) {
            const float4 z4 = make_float4(0.f, 0.f, 0.f, 0.f);
            int kn = k0 + 16 + skk;
            av[0] = (bm + sr0 < M) ? *(const float4*)(A + (size_t)(bm + sr0) * K + kn) : z4;
            av[1] = (bm + sr1 < M) ? *(const float4*)(A + (size_t)(bm + sr1) * K + kn) : z4;
            bv[0] = (bn + sr0 < N) ? *(const float4*)(B + (size_t)(bn + sr0) * K + kn) : z4;
            bv[1] = (bn + sr1 < N) ? *(const float4*)(B + (size_t)(bn + sr1) * K + kn) : z4;
        }

        uint32_t ah[4][4], al[4][4];
#pragma unroll
        for (int mf = 0; mf < 4; mf++) {
            int r0 = wm + mf * 16 + grp;
            ah[mf][0] = Ah[qid    ][r0];
            ah[mf][1] = Ah[qid    ][r0 + 8];
            ah[mf][2] = Ah[qid + 4][r0];
            ah[mf][3] = Ah[qid + 4][r0 + 8];
            al[mf][0] = Al[qid    ][r0];
            al[mf][1] = Al[qid    ][r0 + 8];
            al[mf][2] = Al[qid + 4][r0];
            al[mf][3] = Al[qid + 4][r0 + 8];
        }
        uint32_t bh[4][2], bl[4][2];
#pragma unroll
        for (int nf = 0; nf < 4; nf++) {
            int c0 = wn + nf * 8 + grp;
            bh[nf][0] = Bh[qid    ][c0];
            bh[nf][1] = Bh[qid + 4][c0];
            bl[nf][0] = Bl[qid    ][c0];
            bl[nf][1] = Bl[qid + 4][c0];
        }
#pragma unroll
        for (int mf = 0; mf < 4; mf++)
#pragma unroll
            for (int nf = 0; nf < 4; nf++) {
                MMA_BF16(acc[mf][nf], ah[mf], bh[nf]);
                MMA_BF16(acc[mf][nf], ah[mf], bl[nf]);
                MMA_BF16(acc[mf][nf], al[mf], bh[nf]);
            }
        __syncthreads();
    }

#pragma unroll
    for (int mf = 0; mf < 4; mf++) {
        int gr0 = bm + wm + mf * 16 + grp;
        int gr1 = gr0 + 8;
#pragma unroll
        for (int nf = 0; nf < 4; nf++) {
            int gc = bn + wn + nf * 8 + 2 * qid;
            if (gc < N) {
                if (gr0 < M) {
                    C[(size_t)gr0 * N + gc]     = acc[mf][nf][0];
                    C[(size_t)gr0 * N + gc + 1] = acc[mf][nf][1];
                }
                if (gr1 < M) {
                    C[(size_t)gr1 * N + gc]     = acc[mf][nf][2];
                    C[(size_t)gr1 * N + gc + 1] = acc[mf][nf][3];
                }
            }
        }
    }
}

// ------------------------- last GEMM with fused HK|HV split writeback -------------------------
// C logical [M=NROWS, N=DINNER]; col c<DIMN -> out[row,c]; else second half.
__global__ __launch_bounds__(256) void gemm_nt_tc_split(
    const float* __restrict__ A, const float* __restrict__ B,
    float* __restrict__ out, int M, int N, int K)
{
    __shared__ uint32_t Ah[8][136];
    __shared__ uint32_t Al[8][136];
    __shared__ uint32_t Bh[8][136];
    __shared__ uint32_t Bl[8][136];

    const int tid  = threadIdx.x;
    const int bm   = blockIdx.y * 128;
    const int bn   = blockIdx.x * 128;
    const int lane = tid & 31;
    const int warp = tid >> 5;
    const int wm   = (warp >> 2) * 64;
    const int wn   = (warp & 3) * 32;
    const int grp  = lane >> 2;
    const int qid  = lane & 3;

    const int sr0 = tid >> 2;
    const int sr1 = sr0 + 64;
    const int skk = (tid & 3) << 2;
    const int spp = skk >> 1;

    float acc[4][4][4];
#pragma unroll
    for (int i = 0; i < 4; i++)
#pragma unroll
        for (int j = 0; j < 4; j++)
#pragma unroll
            for (int e = 0; e < 4; e++) acc[i][j][e] = 0.f;

    float4 av[2], bv[2];
    {
        av[0] = *(const float4*)(A + (size_t)(bm + sr0) * K + skk);
        av[1] = *(const float4*)(A + (size_t)(bm + sr1) * K + skk);
        bv[0] = *(const float4*)(B + (size_t)(bn + sr0) * K + skk);
        bv[1] = *(const float4*)(B + (size_t)(bn + sr1) * K + skk);
    }

    for (int k0 = 0; k0 < K; k0 += 16) {
#pragma unroll
        for (int half = 0; half < 2; half++) {
            int r = half ? sr1 : sr0;
            float4 v = av[half];
            float rx, ry, rz, rw;
            Ah[spp    ][r] = pack_hi(v.x, v.y, rx, ry);
            Ah[spp + 1][r] = pack_hi(v.z, v.w, rz, rw);
            Al[spp    ][r] = pack_lo(rx, ry);
            Al[spp + 1][r] = pack_lo(rz, rw);
            v = bv[half];
            Bh[spp    ][r] = pack_hi(v.x, v.y, rx, ry);
            Bh[spp + 1][r] = pack_hi(v.z, v.w, rz, rw);
            Bl[spp    ][r] = pack_lo(rx, ry);
            Bl[spp + 1][r] = pack_lo(rz, rw);
        }
        __syncthreads();

        if (k0 + 16 < K) {
            int kn = k0 + 16 + skk;
            av[0] = *(const float4*)(A + (size_t)(bm + sr0) * K + kn);
            av[1] = *(const float4*)(A + (size_t)(bm + sr1) * K + kn);
            bv[0] = *(const float4*)(B + (size_t)(bn + sr0) * K + kn);
            bv[1] = *(const float4*)(B + (size_t)(bn + sr1) * K + kn);
        }

        uint32_t ah[4][4], al[4][4];
#pragma unroll
        for (int mf = 0; mf < 4; mf++) {
            int r0 = wm + mf * 16 + grp;
            ah[mf][0] = Ah[qid    ][r0];
            ah[mf][1] = Ah[qid    ][r0 + 8];
            ah[mf][2] = Ah[qid + 4][r0];
            ah[mf][3] = Ah[qid + 4][r0 + 8];
            al[mf][0] = Al[qid    ][r0];
            al[mf][1] = Al[qid    ][r0 + 8];
            al[mf][2] = Al[qid + 4][r0];
            al[mf][3] = Al[qid + 4][r0 + 8];
        }
        uint32_t bh[4][2], bl[4][2];
#pragma unroll
        for (int nf = 0; nf < 4; nf++) {
            int c0 = wn + nf * 8 + grp;
            bh[nf][0] = Bh[qid    ][c0];
            bh[nf][1] = Bh[qid + 4][c0];
            bl[nf][0] = Bl[qid    ][c0];
            bl[nf][1] = Bl[qid + 4][c0];
        }
#pragma unroll
        for (int mf = 0; mf < 4; mf++)
#pragma unroll
            for (int nf = 0; nf < 4; nf++) {
                MMA_BF16(acc[mf][nf], ah[mf], bh[nf]);
                MMA_BF16(acc[mf][nf], ah[mf], bl[nf]);
                MMA_BF16(acc[mf][nf], al[mf], bh[nf]);
            }
        __syncthreads();
    }

#pragma unroll
    for (int mf = 0; mf < 4; mf++) {
        int gr0 = bm + wm + mf * 16 + grp;
        int gr1 = gr0 + 8;
#pragma unroll
        for (int nf = 0; nf < 4; nf++) {
            int gc = bn + wn + nf * 8 + 2 * qid;
            size_t off = (gc < DIMN)
                ? (size_t)gr0 * DIMN + gc
                : (size_t)NROWS * DIMN + (size_t)gr0 * DIMN + (gc - DIMN);
            out[off]     = acc[mf][nf][0];
            out[off + 1] = acc[mf][nf][1];
            size_t off1 = off + (size_t)8 * DIMN;
            out[off1]     = acc[mf][nf][2];
            out[off1 + 1] = acc[mf][nf][3];
        }
    }
}

// ------------------------- dt = softplus(dt_raw + dt_bias) -------------------------
__global__ void dt_kernel(const float* __restrict__ dt_bias)
{
    int idx = blockIdx.x * blockDim.x + threadIdx.x;
    if (idx >= NROWS * NHEADSN) return;
    int h = idx & (NHEADSN - 1);
    int row = idx >> 5;
    float v = g_zxbcdt[(size_t)row * DPROJ + (DINNER + CONVD) + h] + dt_bias[h];
    float sp = (v > 20.f) ? v : log1pf(expf(v));
    g_dt[idx] = sp;
}

// ------------------------- depthwise causal conv (w=4) + bias + SiLU -------------------------
__global__ void conv_silu_kernel(const float* __restrict__ cw, const float* __restrict__ cb)
{
    size_t idx = (size_t)blockIdx.x * blockDim.x + threadIdx.x;
    if (idx >= (size_t)NROWS * CONVD) return;
    int c = (int)(idx % CONVD);
    size_t bl = idx / CONVD;
    int l = (int)(bl % SEQLENN);
    int b = (int)(bl / SEQLENN);
    float acc = cb[c];
#pragma unroll
    for (int k = 0; k < DCONVN; k++) {
        int lt = l - (DCONVN - 1) + k;
        if (lt >= 0)
            acc = fmaf(cw[c * DCONVN + k],
                       g_zxbcdt[(size_t)(b * SEQLENN + lt) * DPROJ + DINNER + c], acc);
    }
    float sg = 1.f / (1.f + expf(-acc));
    g_xBCc[idx] = acc * sg;
}

// ------------------------- pass 1: per-segment local scan -------------------------
__global__ __launch_bounds__(256) void scan_seg_kernel(const float* __restrict__ A_log)
{
    const int bid = blockIdx.x;
    const int seg = bid & (NSEG - 1);
    const int h   = (bid >> 4) & (NHEADSN - 1);
    const int b   = bid >> 9;
    const int tid = threadIdx.x;
    const int p   = tid >> 2;
    const int sub = tid & 3;
    const float Ah = -expf(A_log[h]);
    const int bh = b * NHEADSN + h;
    const int rbase = b * SEQLENN + seg * SEGL;

    __shared__ __align__(16) float s_x[TCH][64];
    __shared__ __align__(16) float s_B[TCH][64];
    __shared__ __align__(16) float s_C[TCH][64];
    __shared__ __align__(16) float s_y[TCH][64];
    __shared__ float s_dt[TCH];
    __shared__ float s_dA[TCH];
    __shared__ float s_ac[TCH];
    __shared__ float s_run;

    if (tid == 0) s_run = 1.f;

    float hreg[16];
#pragma unroll
    for (int j = 0; j < 16; j++) hreg[j] = 0.f;

    for (int t0 = 0; t0 < SEGL; t0 += TCH) {
        for (int i = tid; i < TCH * 64; i += 256) {
            int t = i >> 6, pp = i & 63;
            size_t ro = (size_t)(rbase + t0 + t) * CONVD;
            s_x[t][pp] = g_xBCc[ro + h * 64 + pp];
            s_B[t][pp] = g_xBCc[ro + DINNER + pp];
            s_C[t][pp] = g_xBCc[ro + DINNER + DSTATE + pp];
        }
        if (tid < TCH) {
            float dtv = g_dt[(size_t)(rbase + t0 + tid) * NHEADSN + h];
            s_dt[tid] = dtv;
            s_dA[tid] = expf(dtv * Ah);
        }
        __syncthreads();
        if (tid == 0) {
            float run = s_run;
#pragma unroll
            for (int t = 0; t < TCH; t++) { run *= s_dA[t]; s_ac[t] = run; }
            s_run = run;
        }
#pragma unroll 2
        for (int t = 0; t < TCH; t++) {
            float dA = s_dA[t];
            float dtx = s_dt[t] * s_x[t][p];
            float y = 0.f;
            const float4* Bq = (const float4*)&s_B[t][sub * 16];
            const float4* Cq = (const float4*)&s_C[t][sub * 16];
#pragma unroll
            for (int q = 0; q < 4; q++) {
                float4 Bv = Bq[q];
                float4 Cv = Cq[q];
                hreg[q*4+0] = fmaf(hreg[q*4+0], dA, dtx * Bv.x); y = fmaf(hreg[q*4+0], Cv.x, y);
                hreg[q*4+1] = fmaf(hreg[q*4+1], dA, dtx * Bv.y); y = fmaf(hreg[q*4+1], Cv.y, y);
                hreg[q*4+2] = fmaf(hreg[q*4+2], dA, dtx * Bv.z); y = fmaf(hreg[q*4+2], Cv.z, y);
                hreg[q*4+3] = fmaf(hreg[q*4+3], dA, dtx * Bv.w); y = fmaf(hreg[q*4+3], Cv.w, y);
            }
            y += __shfl_down_sync(0xffffffffu, y, 2, 4);
            y += __shfl_down_sync(0xffffffffu, y, 1, 4);
            if (sub == 0) s_y[t][p] = y;
        }
        __syncthreads();
        for (int i = tid; i < TCH * 64; i += 256) {
            int t = i >> 6, pp = i & 63;
            g_y[(size_t)(rbase + t0 + t) * DINNER + h * 64 + pp] = s_y[t][pp];
        }
        if (tid < TCH)
            g_acum[(size_t)bh * SEQLENN + seg * SEGL + t0 + tid] = s_ac[tid];
        __syncthreads();
    }

    float* st = g_state + ((size_t)bh * NSEG + seg) * (64 * DSTATE) + p * DSTATE + sub * 16;
#pragma unroll
    for (int q = 0; q < 4; q++)
        *(float4*)(st + q * 4) = make_float4(hreg[q*4+0], hreg[q*4+1], hreg[q*4+2], hreg[q*4+3]);
}

// ------------------------- pass 2: prefix over segment states -------------------------
__global__ __launch_bounds__(256) void state_combine_kernel()
{
    const int bh = blockIdx.x;
    const int tid = threadIdx.x;
    const size_t base = (size_t)bh * NSEG * (64 * DSTATE);
    float4 hin[4];
#pragma unroll
    for (int q = 0; q < 4; q++) hin[q] = make_float4(0.f, 0.f, 0.f, 0.f);

    for (int seg = 1; seg < NSEG; seg++) {
        float ap = g_acum[(size_t)bh * SEQLENN + seg * SEGL - 1];
        const float4* sl = (const float4*)(g_state + base + (size_t)(seg - 1) * (64 * DSTATE) + tid * 16);
        float4* ho = (float4*)(g_hin + base + (size_t)seg * (64 * DSTATE) + tid * 16);
#pragma unroll
        for (int q = 0; q < 4; q++) {
            float4 s = sl[q];
            hin[q].x = fmaf(hin[q].x, ap, s.x);
            hin[q].y = fmaf(hin[q].y, ap, s.y);
            hin[q].z = fmaf(hin[q].z, ap, s.z);
            hin[q].w = fmaf(hin[q].w, ap, s.w);
            ho[q] = hin[q];
        }
    }
}

// ------------------------- pass 3 (MMA): y += (C .* acum) @ H_in^T -------------------------
// One block per (b,h,seg>=1): Y[256t x 64p] += W[256t x 64n] @ Hin[64p x 64n]^T.
// 256 threads, 8 warps: wm=(warp>>1)*64, wn=(warp&1)*32. bf16 3-split.
__global__ __launch_bounds__(256) void carry_mma_kernel()
{
    const int bid = blockIdx.x;
    const int seg = 1 + (bid % (NSEG - 1));
    const int bh  = bid / (NSEG - 1);
    const int h   = bh & (NHEADSN - 1);
    const int b   = bh >> 5;
    const int rbase = b * SEQLENN + seg * SEGL;

    const int tid  = threadIdx.x;
    const int lane = tid & 31;
    const int warp = tid >> 5;
    const int wm   = (warp >> 1) * 64;   // 0,64,128,192
    const int wn   = (warp & 1) * 32;    // 0,32
    const int grp  = lane >> 2;
    const int qid  = lane & 3;

    __shared__ uint32_t Ah[8][264];      // [kpair][t]
    __shared__ uint32_t Al[8][264];
    __shared__ uint32_t Bh2[32][72];     // [kpair over all 64 n][p]
    __shared__ uint32_t Bl2[32][72];

    // stage Hin (hi/lo) once
    {
        const float* hi = g_hin + ((size_t)bh * NSEG + seg) * (64 * DSTATE);
        for (int i = tid; i < 64 * 32; i += 256) {
            int p  = i >> 5;
            int kp = i & 31;
            float a0 = hi[p * DSTATE + kp * 2];
            float a1 = hi[p * DSTATE + kp * 2 + 1];
            float r0, r1;
            Bh2[kp][p] = pack_hi(a0, a1, r0, r1);
            Bl2[kp][p] = pack_lo(r0, r1);
        }
    }

    float acc[4][4][4];
#pragma unroll
    for (int i = 0; i < 4; i++)
#pragma unroll
        for (int j = 0; j < 4; j++)
#pragma unroll
            for (int e = 0; e < 4; e++) acc[i][j][e] = 0.f;

    for (int k0 = 0; k0 < DSTATE; k0 += 16) {
        // stage W[t][k0..k0+15] = C[t][..] * acum[t]
#pragma unroll
        for (int ld = 0; ld < 4; ld++) {
            int idx = tid + ld * 256;            // 0..1023
            int r = idx >> 2;                    // t: 0..255
            int kk = (idx & 3) << 2;
            float al = g_acum[(size_t)bh * SEQLENN + seg * SEGL + r];
            float4 v = *(const float4*)(g_xBCc + (size_t)(rbase + r) * CONVD + DINNER + DSTATE + k0 + kk);
            v.x *= al; v.y *= al; v.z *= al; v.w *= al;
            int spp = kk >> 1;
            float r0, r1, r2, r3;
            Ah[spp    ][r] = pack_hi(v.x, v.y, r0, r1);
            Ah[spp + 1][r] = pack_hi(v.z, v.w, r2, r3);
            Al[spp    ][r] = pack_lo(r0, r1);
            Al[spp + 1][r] = pack_lo(r2, r3);
        }
        __syncthreads();

        const int kb = k0 >> 1;   // kpair base into Bh2
        uint32_t ah[4][4], al[4][4];
#pragma unroll
        for (int mf = 0; mf < 4; mf++) {
            int r0 = wm + mf * 16 + grp;
            ah[mf][0] = Ah[qid    ][r0];
            ah[mf][1] = Ah[qid    ][r0 + 8];
            ah[mf][2] = Ah[qid + 4][r0];
            ah[mf][3] = Ah[qid + 4][r0 + 8];
            al[mf][0] = Al[qid    ][r0];
            al[mf][1] = Al[qid    ][r0 + 8];
            al[mf][2] = Al[qid + 4][r0];
            al[mf][3] = Al[qid + 4][r0 + 8];
        }
        uint32_t bh[4][2], bl[4][2];
#pragma unroll
        for (int nf = 0; nf < 4; nf++) {
            int c0 = wn + nf * 8 + grp;
            bh[nf][0] = Bh2[kb + qid    ][c0];
            bh[nf][1] = Bh2[kb + qid + 4][c0];
            bl[nf][0] = Bl2[kb + qid    ][c0];
            bl[nf][1] = Bl2[kb + qid + 4][c0];
        }
#pragma unroll
        for (int mf = 0; mf < 4; mf++)
#pragma unroll
            for (int nf = 0; nf < 4; nf++) {
                MMA_BF16(acc[mf][nf], ah[mf], bh[nf]);
                MMA_BF16(acc[mf][nf], ah[mf], bl[nf]);
                MMA_BF16(acc[mf][nf], al[mf], bh[nf]);
            }
        __syncthreads();
    }

    // accumulate into g_y
#pragma unroll
    for (int mf = 0; mf < 4; mf++) {
        int t0 = wm + mf * 16 + grp;
        int t1 = t0 + 8;
#pragma unroll
        for (int nf = 0; nf < 4; nf++) {
            int gp = wn + nf * 8 + 2 * qid;
            size_t o0 = (size_t)(rbase + t0) * DINNER + h * 64 + gp;
            size_t o1 = (size_t)(rbase + t1) * DINNER + h * 64 + gp;
            g_y[o0]     += acc[mf][nf][0];
            g_y[o0 + 1] += acc[mf][nf][1];
            g_y[o1]     += acc[mf][nf][2];
            g_y[o1 + 1] += acc[mf][nf][3];
        }
    }
}

// ------------------------- D*x, gate with silu(z), RMSNorm -------------------------
__global__ __launch_bounds__(256) void gate_norm_kernel(
    const float* __restrict__ Dp, const float* __restrict__ norm_w)
{
    const int row = blockIdx.x;
    const int tid = threadIdx.x;
    float vals[8];
    float ss = 0.f;
#pragma unroll
    for (int j = 0; j < 8; j++) {
        int c = tid + j * 256;
        float y = g_y[(size_t)row * DINNER + c];
        int hh = c >> 6;
        float xv = g_xBCc[(size_t)row * CONVD + c];
        y = fmaf(Dp[hh], xv, y);
        float zv = g_zxbcdt[(size_t)row * DPROJ + c];
        float g = zv / (1.f + expf(-zv));
        float v = y * g;
        vals[j] = v;
        ss = fmaf(v, v, ss);
    }
    __shared__ float red[32];
    for (int o = 16; o; o >>= 1) ss += __shfl_down_sync(0xffffffffu, ss, o);
    if ((tid & 31) == 0) red[tid >> 5] = ss;
    __syncthreads();
    if (tid < 32) {
        float s2 = (tid < 8) ? red[tid] : 0.f;
        for (int o = 4; o; o >>= 1) s2 += __shfl_down_sync(0xffffffffu, s2, o);
        if (tid == 0) red[0] = s2;
    }
    __syncthreads();
    float scale = rsqrtf(red[0] / (float)DINNER + EPSV);
#pragma unroll
    for (int j = 0; j < 8; j++) {
        int c = tid + j * 256;
        g_yn[(size_t)row * DINNER + c] = vals[j] * scale * norm_w[c];
    }
}

// ------------------------- launch -------------------------
extern "C" void kernel_launch(void* const* d_in, const int* in_sizes, int n_in,
                              void* d_out, int out_size)
{
    const float* X          = (const float*)d_in[0];
    const float* in_proj_w  = (const float*)d_in[1];
    const float* conv_w     = (const float*)d_in[2];
    const float* conv_b     = (const float*)d_in[3];
    const float* dt_bias    = (const float*)d_in[4];
    const float* A_log      = (const float*)d_in[5];
    const float* Dp         = (const float*)d_in[6];
    const float* norm_w     = (const float*)d_in[7];
    const float* out_proj_w = (const float*)d_in[8];
    const float* to_h_w     = (const float*)d_in[9];
    float* out = (float*)d_out;

    float *zx, *yn, *H;
    cudaGetSymbolAddress((void**)&zx,  g_zxbcdt);
    cudaGetSymbolAddress((void**)&yn,  g_yn);
    cudaGetSymbolAddress((void**)&H,   g_H);

    // 1) zxbcdt = X @ in_proj_w^T
    gemm_nt_tc<<<dim3((DPROJ + 127) / 128, NROWS / 128), 256>>>(X, in_proj_w, zx, NROWS, DPROJ, DIMN);
    // 2) dt = softplus(dt_raw + bias)
    dt_kernel<<<(NROWS * NHEADSN + 255) / 256, 256>>>(dt_bias);
    // 3) depthwise conv + silu
    conv_silu_kernel<<<(int)(((size_t)NROWS * CONVD + 255) / 256), 256>>>(conv_w, conv_b);
    // 4) segmented scan: local pass, state prefix, MMA carry
    scan_seg_kernel<<<BATCHN * NHEADSN * NSEG, 256>>>(A_log);
    state_combine_kernel<<<BATCHN * NHEADSN, 256>>>();
    carry_mma_kernel<<<BATCHN * NHEADSN * (NSEG - 1), 256>>>();
    // 5) gate + rmsnorm
    gate_norm_kernel<<<NROWS, 256>>>(Dp, norm_w);
    // 6) H = yn @ out_proj_w^T
    gemm_nt_tc<<<dim3(DIMN / 128, NROWS / 128), 256>>>(yn, out_proj_w, H, NROWS, DIMN, DINNER);
    // 7) HKV = H @ to_h_w^T, fused split into out
    gemm_nt_tc_split<<<dim3(DINNER / 128, NROWS / 128), 256>>>(H, to_h_w, out, NROWS, DINNER, DIMN);
}